// round 3
// baseline (speedup 1.0000x reference)
#include <cuda_runtime.h>
#include <math.h>

// ---------------------------------------------------------------------------
// Problem constants
// ---------------------------------------------------------------------------
#define W_IN   3840
#define H_IN   2160
#define NCH    3
#define HMSZ   256      // HM
#define MSZ    64       // mask size
#define KMAX   256
#define NCLS   7
#define FILLV  (-1000000)

// Output section offsets (float32 concatenation of the reference tuple)
#define OFF_HEAT    0
#define OFF_COORDS  (HMSZ*HMSZ)                 // 65536
#define OFF_SURV    (OFF_COORDS + KMAX*2)       // 66048
#define OFF_LOGITS  (OFF_SURV + KMAX)           // 66304
#define OFF_LABELS  (OFF_LOGITS + KMAX*NCLS)    // 68096

// ---------------------------------------------------------------------------
// Scratch (static __device__ arrays — no allocations allowed)
// ---------------------------------------------------------------------------
__device__ float g_A[NCH * H_IN * HMSZ];   // horizontal-resized to 256 cols (6.6 MB)
__device__ float g_B[NCH * H_IN * MSZ];    // horizontal-resized to 64 cols  (1.66 MB)
__device__ float g_hx[NCH * HMSZ * HMSZ];  // h_x (3,256,256)
__device__ float g_mx[NCH * MSZ * MSZ];    // m_x (3,64,64)
__device__ float g_mk[MSZ * MSZ];          // thresholded mask conv (64,64)
__device__ float g_heat[HMSZ * HMSZ];      // heatmap
__device__ int   g_ri[KMAX];
__device__ int   g_ci[KMAX];
__device__ int   g_surv[KMAX];

// ---------------------------------------------------------------------------
// K1: horizontal antialiased bilinear resize: x row (3840) -> 256 cols (A)
//     and 64 cols (B). One block per (row, channel). Reads x exactly once.
//     Matches jax.image.resize(antialias=True, 'bilinear') weight math:
//       center = (o+0.5)*inv - 0.5 ; w = max(0, 1-|center-j|/inv), normalized.
// ---------------------------------------------------------------------------
__global__ __launch_bounds__(320) void hresize_kernel(const float* __restrict__ x) {
    const int row = blockIdx.x;
    const int ch  = blockIdx.y;
    __shared__ float srow[W_IN];

    const float4* src = (const float4*)(x + ((size_t)ch * H_IN + row) * W_IN);
    float4* s4 = (float4*)srow;
    #pragma unroll
    for (int i = threadIdx.x; i < W_IN / 4; i += 320) s4[i] = src[i];
    __syncthreads();

    const int t = threadIdx.x;
    if (t < 256) {
        const float inv  = 15.0f;                 // 3840/256 (exact)
        const float rinv = 1.0f / inv;
        float center = (t + 0.5f) * inv - 0.5f;
        int j0 = max(0, (int)ceilf(center - inv));
        int j1 = min(W_IN - 1, (int)floorf(center + inv));
        float sw = 0.f, sv = 0.f;
        for (int j = j0; j <= j1; ++j) {
            float w = fmaxf(0.f, 1.0f - fabsf(center - (float)j) * rinv);
            sw += w; sv += w * srow[j];
        }
        g_A[((size_t)ch * H_IN + row) * HMSZ + t] = sv / sw;
    } else {
        const int o = t - 256;                    // 0..63
        const float inv  = 60.0f;                 // 3840/64 (exact)
        const float rinv = 1.0f / inv;
        float center = (o + 0.5f) * inv - 0.5f;
        int j0 = max(0, (int)ceilf(center - inv));
        int j1 = min(W_IN - 1, (int)floorf(center + inv));
        float sw = 0.f, sv = 0.f;
        for (int j = j0; j <= j1; ++j) {
            float w = fmaxf(0.f, 1.0f - fabsf(center - (float)j) * rinv);
            sw += w; sv += w * srow[j];
        }
        g_B[((size_t)ch * H_IN + row) * MSZ + o] = sv / sw;
    }
}

// ---------------------------------------------------------------------------
// K2a: vertical resize 2160 -> 256 on g_A  -> g_hx
// ---------------------------------------------------------------------------
__global__ __launch_bounds__(256) void vresize_h_kernel() {
    const int col  = threadIdx.x;   // 0..255
    const int rout = blockIdx.x;    // 0..255
    const int ch   = blockIdx.y;    // 0..2
    const float inv  = 8.4375f;     // 2160/256 (exact in fp32)
    const float rinv = 1.0f / inv;
    float center = (rout + 0.5f) * inv - 0.5f;
    int j0 = max(0, (int)ceilf(center - inv));
    int j1 = min(H_IN - 1, (int)floorf(center + inv));
    const float* base = g_A + (size_t)ch * H_IN * HMSZ + col;
    float sw = 0.f, sv = 0.f;
    for (int j = j0; j <= j1; ++j) {
        float w = fmaxf(0.f, 1.0f - fabsf(center - (float)j) * rinv);
        sw += w; sv += w * base[(size_t)j * HMSZ];
    }
    g_hx[(ch * HMSZ + rout) * HMSZ + col] = sv / sw;
}

// ---------------------------------------------------------------------------
// K2b: vertical resize 2160 -> 64 on g_B -> g_mx
// ---------------------------------------------------------------------------
__global__ __launch_bounds__(64) void vresize_m_kernel() {
    const int col  = threadIdx.x;   // 0..63
    const int rout = blockIdx.x;    // 0..63
    const int ch   = blockIdx.y;
    const float inv  = 33.75f;      // 2160/64 (exact in fp32)
    const float rinv = 1.0f / inv;
    float center = (rout + 0.5f) * inv - 0.5f;
    int j0 = max(0, (int)ceilf(center - inv));
    int j1 = min(H_IN - 1, (int)floorf(center + inv));
    const float* base = g_B + (size_t)ch * H_IN * MSZ + col;
    float sw = 0.f, sv = 0.f;
    for (int j = j0; j <= j1; ++j) {
        float w = fmaxf(0.f, 1.0f - fabsf(center - (float)j) * rinv);
        sw += w; sv += w * base[(size_t)j * MSZ];
    }
    g_mx[(ch * MSZ + rout) * MSZ + col] = sv / sw;
}

// ---------------------------------------------------------------------------
// K3a: mask conv (3x3 SAME, cross-correlation) + clip[0,1] + threshold 0.6
// ---------------------------------------------------------------------------
__global__ __launch_bounds__(256) void mask_kernel(const float* __restrict__ mw,
                                                   const float* __restrict__ mb) {
    int idx = blockIdx.x * 256 + threadIdx.x;     // 0..4095
    int r = idx >> 6, c = idx & 63;
    float acc = mb[0];
    #pragma unroll
    for (int ch = 0; ch < NCH; ++ch) {
        #pragma unroll
        for (int kh = 0; kh < 3; ++kh) {
            int rr = r + kh - 1;
            if (rr < 0 || rr >= MSZ) continue;
            #pragma unroll
            for (int kw = 0; kw < 3; ++kw) {
                int cc = c + kw - 1;
                if (cc < 0 || cc >= MSZ) continue;
                acc += g_mx[(ch * MSZ + rr) * MSZ + cc] * mw[ch * 9 + kh * 3 + kw];
            }
        }
    }
    acc = fminf(fmaxf(acc, 0.0f), 1.0f);
    if (acc < 0.6f) acc = 0.0f;
    g_mk[idx] = acc;
}

// ---------------------------------------------------------------------------
// K3b: loc conv + clip + threshold 0.4, multiplied by 4x-upsampled mask
//      -> heatmap (written to scratch AND d_out)
// ---------------------------------------------------------------------------
__global__ __launch_bounds__(256) void heat_kernel(const float* __restrict__ lw,
                                                   const float* __restrict__ lb,
                                                   float* __restrict__ out) {
    const int r = blockIdx.x;
    const int c = threadIdx.x;
    float acc = lb[0];
    #pragma unroll
    for (int ch = 0; ch < NCH; ++ch) {
        #pragma unroll
        for (int kh = 0; kh < 3; ++kh) {
            int rr = r + kh - 1;
            if (rr < 0 || rr >= HMSZ) continue;
            #pragma unroll
            for (int kw = 0; kw < 3; ++kw) {
                int cc = c + kw - 1;
                if (cc < 0 || cc >= HMSZ) continue;
                acc += g_hx[(ch * HMSZ + rr) * HMSZ + cc] * lw[ch * 9 + kh * 3 + kw];
            }
        }
    }
    acc = fminf(fmaxf(acc, 0.0f), 1.0f);
    if (acc < 0.4f) acc = 0.0f;
    float h = acc * g_mk[(r >> 2) * MSZ + (c >> 2)];
    g_heat[r * HMSZ + c] = h;
    out[OFF_HEAT + r * HMSZ + c] = h;
}

// ---------------------------------------------------------------------------
// K4: strict 4-neighbor peak detection (zero-padded borders) + ORDERED
//     row-major compaction (matches jnp.nonzero(size=256, fill=-1e6)).
//     Single block, 1024 threads, 64 sequential chunks with block-wide scan.
// ---------------------------------------------------------------------------
__global__ __launch_bounds__(1024) void peaks_kernel(float* __restrict__ out) {
    __shared__ int s_base;
    __shared__ int s_wcnt[32];
    const int tid  = threadIdx.x;
    const int lane = tid & 31;
    const int warp = tid >> 5;
    if (tid == 0) s_base = 0;
    __syncthreads();

    for (int chunk = 0; chunk < 64; ++chunk) {
        int idx = chunk * 1024 + tid;
        int r = idx >> 8, c = idx & 255;
        float v  = g_heat[idx];
        float rt = (c < 255) ? g_heat[idx + 1]   : 0.f;
        float lf = (c > 0)   ? g_heat[idx - 1]   : 0.f;
        float dn = (r < 255) ? g_heat[idx + 256] : 0.f;
        float up = (r > 0)   ? g_heat[idx - 256] : 0.f;
        bool pk = (v > rt) && (v > lf) && (v > dn) && (v > up);

        unsigned bal = __ballot_sync(0xffffffffu, pk);
        int woff = __popc(bal & ((1u << lane) - 1u));
        if (lane == 0) s_wcnt[warp] = __popc(bal);
        __syncthreads();
        int prefix = 0;
        for (int w = 0; w < warp; ++w) prefix += s_wcnt[w];
        int slot = s_base + prefix + woff;
        if (pk && slot < KMAX) { g_ri[slot] = r; g_ci[slot] = c; }
        __syncthreads();
        if (tid == 0) {
            int tot = 0;
            for (int w = 0; w < 32; ++w) tot += s_wcnt[w];
            s_base += tot;
        }
        __syncthreads();
    }

    int n = s_base;
    if (tid < KMAX && tid >= n) { g_ri[tid] = FILLV; g_ci[tid] = FILLV; }
    __syncthreads();
    if (tid < KMAX) {
        out[OFF_COORDS + 2 * tid]     = (float)g_ri[tid];
        out[OFF_COORDS + 2 * tid + 1] = (float)g_ci[tid];
    }
}

// ---------------------------------------------------------------------------
// K5: pairwise d^2 in fp32 (including FILL rows, exactly like the reference);
//     reject if any valid peak at 1 < d2 < 9. survive = valid & ~reject.
// ---------------------------------------------------------------------------
__global__ __launch_bounds__(256) void survive_kernel(float* __restrict__ out) {
    __shared__ float sr[KMAX], sc[KMAX];
    __shared__ int   sval[KMAX];
    const int j = threadIdx.x;
    int rij = g_ri[j], cij = g_ci[j];
    sr[j] = (float)rij; sc[j] = (float)cij;
    sval[j] = (rij > FILLV) ? 1 : 0;
    __syncthreads();
    float rj = sr[j], cj = sc[j];
    bool rej = false;
    #pragma unroll 4
    for (int i = 0; i < KMAX; ++i) {
        float dr = sr[i] - rj, dc = sc[i] - cj;
        float d2 = dr * dr + dc * dc;
        if (sval[i] && d2 > 1.0f && d2 < 9.0f) rej = true;
    }
    int s = (sval[j] && !rej) ? 1 : 0;
    g_surv[j] = s;
    out[OFF_SURV + j] = (float)s;
}

// ---------------------------------------------------------------------------
// K6: per-peak 32x32x3 window gather (implicit 16-pad of h_x[0]) ->
//     3072x7 matmul -> softmax * survive -> logits + argmax label.
// ---------------------------------------------------------------------------
__global__ __launch_bounds__(256) void classify_kernel(const float* __restrict__ lw,
                                                       const float* __restrict__ lb,
                                                       float* __restrict__ out) {
    const int k = blockIdx.x;
    const int t = threadIdx.x;
    __shared__ float red[NCLS * 256];   // 7 KB

    int r0 = min(max(g_ri[k], 0), HMSZ - 1);
    int c0 = min(max(g_ci[k], 0), HMSZ - 1);

    float acc[NCLS];
    #pragma unroll
    for (int q = 0; q < NCLS; ++q) acc[q] = 0.f;

    for (int i = t; i < 3 * 32 * 32; i += 256) {
        int ch = i >> 10, rem = i & 1023;
        int wr = rem >> 5, wc = rem & 31;
        int gr = r0 + wr - 16, gc = c0 + wc - 16;
        float v = 0.f;
        if (gr >= 0 && gr < HMSZ && gc >= 0 && gc < HMSZ)
            v = g_hx[(ch << 16) + (gr << 8) + gc];
        const float* wrow = lw + (size_t)i * NCLS;
        #pragma unroll
        for (int q = 0; q < NCLS; ++q) acc[q] += v * wrow[q];
    }
    #pragma unroll
    for (int q = 0; q < NCLS; ++q) red[q * 256 + t] = acc[q];
    __syncthreads();
    for (int s = 128; s > 0; s >>= 1) {
        if (t < s) {
            #pragma unroll
            for (int q = 0; q < NCLS; ++q) red[q * 256 + t] += red[q * 256 + t + s];
        }
        __syncthreads();
    }
    if (t == 0) {
        float z[NCLS];
        #pragma unroll
        for (int q = 0; q < NCLS; ++q) z[q] = red[q * 256] + lb[q];
        float m = z[0];
        #pragma unroll
        for (int q = 1; q < NCLS; ++q) m = fmaxf(m, z[q]);
        float se = 0.f;
        #pragma unroll
        for (int q = 0; q < NCLS; ++q) se += expf(z[q] - m);
        float lse = logf(se);
        float sflag = (float)g_surv[k];
        float best = -1.0f; int bi = 0;
        #pragma unroll
        for (int q = 0; q < NCLS; ++q) {
            float lg = expf(z[q] - m - lse) * sflag;
            out[OFF_LOGITS + k * NCLS + q] = lg;
            if (lg > best) { best = lg; bi = q; }
        }
        out[OFF_LABELS + k] = (float)bi;
    }
}

// ---------------------------------------------------------------------------
// Launch
// ---------------------------------------------------------------------------
extern "C" void kernel_launch(void* const* d_in, const int* in_sizes, int n_in,
                              void* d_out, int out_size) {
    const float* x       = (const float*)d_in[0];
    const float* loc_w   = (const float*)d_in[1];
    const float* loc_b   = (const float*)d_in[2];
    const float* mask_w  = (const float*)d_in[3];
    const float* mask_b  = (const float*)d_in[4];
    const float* label_w = (const float*)d_in[5];
    const float* label_b = (const float*)d_in[6];
    float* out = (float*)d_out;

    hresize_kernel<<<dim3(H_IN, NCH), 320>>>(x);
    vresize_h_kernel<<<dim3(HMSZ, NCH), 256>>>();
    vresize_m_kernel<<<dim3(MSZ, NCH), 64>>>();
    mask_kernel<<<16, 256>>>(mask_w, mask_b);
    heat_kernel<<<HMSZ, 256>>>(loc_w, loc_b, out);
    peaks_kernel<<<1, 1024>>>(out);
    survive_kernel<<<1, 256>>>(out);
    classify_kernel<<<KMAX, 256>>>(label_w, label_b, out);
}